// round 17
// baseline (speedup 1.0000x reference)
#include <cuda_runtime.h>
#include <cuda_bf16.h>
#include <cuda_fp16.h>
#include <cstdint>

// Problem constants
#define NN 100000
#define FD 128
#define NEMAX 1600000
#define SCAN_BS 256
#define NB1 ((NN + SCAN_BS - 1) / SCAN_BS)   // 391

// ---------------- Scratch (static __device__, device-code access only) ------
__device__ __half g_hh[(size_t)NN * FD];    // GEMM output / messages (fp16)
__device__ __half g_aggh[(size_t)NN * FD];  // layer-1 activation * ns (fp16)
__device__ int   g_co[NN];                  // out-degree
__device__ int   g_ci[NN];                  // in-degree
__device__ int   g_rowptr[NN + 1];
__device__ int   g_cursor[NN];
__device__ int   g_esrc[NEMAX];
__device__ int   g_bsum[NB1];
// Transposed fp16 weights: [n][k]
__device__ __half g_w1h[FD * FD];
__device__ __half g_w2h[FD * FD];

// ---------------- Base-PTX MMA helpers ----------------
__device__ __forceinline__ uint32_t smem_u32(const void* p) {
    uint32_t a;
    asm("{ .reg .u64 t; cvta.to.shared.u64 t, %1; cvt.u32.u64 %0, t; }"
        : "=r"(a) : "l"(p));
    return a;
}
#define LDSM4(r0, r1, r2, r3, addr) \
    asm volatile("ldmatrix.sync.aligned.m8n8.x4.shared.b16 {%0,%1,%2,%3}, [%4];" \
                 : "=r"(r0), "=r"(r1), "=r"(r2), "=r"(r3) : "r"(addr))
#define LDSM2(r0, r1, addr) \
    asm volatile("ldmatrix.sync.aligned.m8n8.x2.shared.b16 {%0,%1}, [%2];" \
                 : "=r"(r0), "=r"(r1) : "r"(addr))
__device__ __forceinline__ void mma16816(float* c, const uint32_t* a, const uint32_t* b) {
    asm volatile("mma.sync.aligned.m16n8k16.row.col.f32.f16.f16.f32 "
                 "{%0,%1,%2,%3}, {%4,%5,%6,%7}, {%8,%9}, {%0,%1,%2,%3};"
                 : "+f"(c[0]), "+f"(c[1]), "+f"(c[2]), "+f"(c[3])
                 : "r"(a[0]), "r"(a[1]), "r"(a[2]), "r"(a[3]),
                   "r"(b[0]), "r"(b[1]));
}

// ---------------- Counters / Degree / CSR (R8-proven) ----------------
__global__ void zero_cnt_kernel(int n) {
    int i = blockIdx.x * blockDim.x + threadIdx.x;
    if (i < n) { g_co[i] = 0; g_ci[i] = 0; }
}
__global__ void degree_kernel(const int* __restrict__ src,
                              const int* __restrict__ dst, int E) {
    int i = blockIdx.x * blockDim.x + threadIdx.x;
    if (i < E) {
        atomicAdd(&g_co[__ldg(&src[i])], 1);
        atomicAdd(&g_ci[__ldg(&dst[i])], 1);
    }
}
__global__ void scan1_kernel(int n) {
    __shared__ int s[SCAN_BS];
    int t = threadIdx.x, i = blockIdx.x * SCAN_BS + t;
    int v = (i < n) ? g_ci[i] : 0;
    s[t] = v; __syncthreads();
#pragma unroll
    for (int off = 1; off < SCAN_BS; off <<= 1) {
        int x = (t >= off) ? s[t - off] : 0; __syncthreads();
        s[t] += x; __syncthreads();
    }
    if (i < n) g_rowptr[i] = s[t] - v;
    if (t == SCAN_BS - 1) g_bsum[blockIdx.x] = s[t];
}
__global__ void scan2_kernel(int nb) {
    __shared__ int s[512];
    int t = threadIdx.x;
    int v = (t < nb) ? g_bsum[t] : 0;
    s[t] = v; __syncthreads();
#pragma unroll
    for (int off = 1; off < 512; off <<= 1) {
        int x = (t >= off) ? s[t - off] : 0; __syncthreads();
        s[t] += x; __syncthreads();
    }
    if (t < nb) g_bsum[t] = s[t] - v;
}
__global__ void scan3_kernel(int n, int E) {
    int i = blockIdx.x * blockDim.x + threadIdx.x;
    if (i < n) {
        int r = g_rowptr[i] + g_bsum[i >> 8];
        g_rowptr[i] = r; g_cursor[i] = r;
    }
    if (i == 0) g_rowptr[n] = E;
}
__global__ void fill_kernel(const int* __restrict__ src,
                            const int* __restrict__ dst, int E) {
    int e = blockIdx.x * blockDim.x + threadIdx.x;
    if (e < E) {
        int pos = atomicAdd(&g_cursor[__ldg(&dst[e])], 1);
        g_esrc[pos] = __ldg(&src[e]);
    }
}

// ---------------- Weight prep: transpose to [n][k], fp16 ----------------
__global__ void prep_w_kernel(const float* __restrict__ W1,
                              const float* __restrict__ W2) {
    int i = blockIdx.x * blockDim.x + threadIdx.x;
    if (i < FD * FD) {
        int k = i >> 7, n = i & 127;
        g_w1h[n * FD + k] = __float2half(W1[i]);
        g_w2h[n * FD + k] = __float2half(W2[i]);
    }
}

// ---------------- Message scale: g_hh[i,:] *= ns[i] (layer 1 only) -----------
__global__ void scale_msg_kernel(int nvec) {
    int i = blockIdx.x * blockDim.x + threadIdx.x;   // nvec = M * 16
    if (i >= nvec) return;
    int node = i >> 4;                               // 16 uint4 per row
    float ns = rsqrtf(fmaxf((float)__ldg(&g_co[node]), 1.f));
    uint4 v = reinterpret_cast<uint4*>(g_hh)[i];
    uint32_t* w = &v.x;
#pragma unroll
    for (int q = 0; q < 4; q++) {
        float2 f = __half22float2(*reinterpret_cast<__half2*>(&w[q]));
        __half2 r = __floats2half2_rn(f.x * ns, f.y * ns);
        w[q] = *reinterpret_cast<uint32_t*>(&r);
    }
    reinterpret_cast<uint4*>(g_hh)[i] = v;
}

// ---------------- fp16 mma.sync GEMM: 128x128 tile, 512 threads --------------
// 16 warps as 4(m) x 4(n); warp tile 32x32 (acc 32 f32/thread -> ~70 regs ->
// 2 CTAs/SM = 32 resident warps, 2x the latency hiding of the 256-thr version).
// Layer 1: A = fp16(features) UNSCALED (ns applied by scale_msg afterwards).
// Layer 2: A = g_aggh (fp16, *ns folded) — straight copy.
#define ASTRIDE 136
#define TILE_B (128 * ASTRIDE * 2)   // 34816 bytes
#define OFF_A 0
#define OFF_B TILE_B
#define GEMM_SMEM (2 * TILE_B)       // 69632 bytes

__global__ __launch_bounds__(512) void gemm_mma_kernel(
    const float* __restrict__ Aext, int layer, int M) {
    extern __shared__ char sm[];
    const uint32_t sb = smem_u32(sm);
    const int tid = threadIdx.x;
    const int lane = tid & 31;
    const int wid = tid >> 5;            // 0..15
    const int row0 = blockIdx.x * 128;

    // ---- Fill A tile: thread handles row tid/4, 32-col quarter ----
    {
        int r = tid >> 2;
        int cs = (tid & 3) * 32;
        int grow = row0 + r;
        uint32_t base = (uint32_t)(r * ASTRIDE + cs) * 2;
        if (layer == 1) {
            if (grow < M) {
                const float4* ap = reinterpret_cast<const float4*>(Aext + (size_t)grow * FD + cs);
#pragma unroll
                for (int j = 0; j < 8; j++) {
                    float4 v = __ldg(&ap[j]);
                    __half2 p0 = __floats2half2_rn(v.x, v.y);
                    __half2 p1 = __floats2half2_rn(v.z, v.w);
                    uint32_t o = base + j * 8;
                    *reinterpret_cast<uint32_t*>(sm + OFF_A + o)     = *reinterpret_cast<uint32_t*>(&p0);
                    *reinterpret_cast<uint32_t*>(sm + OFF_A + o + 4) = *reinterpret_cast<uint32_t*>(&p1);
                }
            } else {
#pragma unroll
                for (int j = 0; j < 8; j++) {
                    uint32_t o = base + j * 8;
                    *reinterpret_cast<uint32_t*>(sm + OFF_A + o)     = 0u;
                    *reinterpret_cast<uint32_t*>(sm + OFF_A + o + 4) = 0u;
                }
            }
        } else {
            if (grow < M) {
                const uint4* ap = reinterpret_cast<const uint4*>(g_aggh + (size_t)grow * FD + cs);
#pragma unroll
                for (int j = 0; j < 4; j++)
                    *reinterpret_cast<uint4*>(sm + OFF_A + base + j * 16) = __ldg(&ap[j]);
            } else {
#pragma unroll
                for (int j = 0; j < 4; j++)
                    *reinterpret_cast<uint4*>(sm + OFF_A + base + j * 16) =
                        make_uint4(0u, 0u, 0u, 0u);
            }
        }
    }
    // ---- Fill B tile from pre-transposed fp16 weights [n][k] ----
    {
        const __half* wh = (layer == 1) ? g_w1h : g_w2h;
        int n = tid >> 2;
        int seg = (tid & 3) * 32;
        uint32_t base = (uint32_t)(n * ASTRIDE + seg) * 2;
        const uint4* ph = reinterpret_cast<const uint4*>(wh + (size_t)n * FD + seg);
#pragma unroll
        for (int j = 0; j < 4; j++)
            *reinterpret_cast<uint4*>(sm + OFF_B + base + j * 16) = __ldg(&ph[j]);
    }
    __syncthreads();

    // ---- Mainloop: warp tile 32x32; warps 4(m) x 4(n) ----
    const int m0 = (wid >> 2) * 32;
    const int n0 = (wid & 3) * 32;

    float acc[2][4][4];
#pragma unroll
    for (int mi = 0; mi < 2; mi++)
#pragma unroll
        for (int ni = 0; ni < 4; ni++)
#pragma unroll
            for (int q = 0; q < 4; q++) acc[mi][ni][q] = 0.f;

    const uint32_t aOff = (uint32_t)((m0 + (lane & 15)) * ASTRIDE + ((lane >> 4) << 3)) * 2;
    const uint32_t bOff = (uint32_t)((n0 + (lane & 7)) * ASTRIDE + (((lane >> 3) & 1) << 3)) * 2;
    const uint32_t aBase = sb + OFF_A + aOff;
    const uint32_t bBase = sb + OFF_B + bOff;

#pragma unroll
    for (int ks = 0; ks < 8; ks++) {
        const uint32_t ka = ks * 32;
        uint32_t a[2][4], b[4][2];
#pragma unroll
        for (int mi = 0; mi < 2; mi++)
            LDSM4(a[mi][0], a[mi][1], a[mi][2], a[mi][3], aBase + mi * (16 * ASTRIDE * 2) + ka);
#pragma unroll
        for (int ni = 0; ni < 4; ni++)
            LDSM2(b[ni][0], b[ni][1], bBase + ni * (8 * ASTRIDE * 2) + ka);
#pragma unroll
        for (int mi = 0; mi < 2; mi++)
#pragma unroll
            for (int ni = 0; ni < 4; ni++)
                mma16816(acc[mi][ni], a[mi], b[ni]);
    }

    // ---- Epilogue: fragment -> g_hh (fp16) ----
    const int rb = m0 + (lane >> 2);
    const int cb = n0 + (lane & 3) * 2;
#pragma unroll
    for (int mi = 0; mi < 2; mi++) {
        int r0g = row0 + rb + mi * 16;
#pragma unroll
        for (int ni = 0; ni < 4; ni++) {
            int col = cb + ni * 8;
            if (r0g < M)
                *reinterpret_cast<__half2*>(g_hh + (size_t)r0g * FD + col) =
                    __floats2half2_rn(acc[mi][ni][0], acc[mi][ni][1]);
            if (r0g + 8 < M)
                *reinterpret_cast<__half2*>(g_hh + (size_t)(r0g + 8) * FD + col) =
                    __floats2half2_rn(acc[mi][ni][2], acc[mi][ni][3]);
        }
    }
}

// ---------------- CSR aggregate (R8-proven verbatim) -------------------------
// Layer 1 (out==nullptr): g_aggh = fp16(relu(acc*nd + b) * ns)
// Layer 2: out = acc*nd + b  (fp32)
__global__ __launch_bounds__(256) void agg_kernel(
    const float* __restrict__ bvec, float* __restrict__ out, int M) {
    const int warp = (blockIdx.x * blockDim.x + threadIdx.x) >> 5;
    const int lane = threadIdx.x & 31;
    if (warp >= M) return;

    const int beg = __ldg(&g_rowptr[warp]);
    const int end = __ldg(&g_rowptr[warp + 1]);

    float4 acc = make_float4(0.f, 0.f, 0.f, 0.f);
    int j = beg;
    for (; j + 3 < end; j += 4) {
        int s0 = __ldg(&g_esrc[j]);
        int s1 = __ldg(&g_esrc[j + 1]);
        int s2 = __ldg(&g_esrc[j + 2]);
        int s3 = __ldg(&g_esrc[j + 3]);
        uint2 u0 = __ldg(reinterpret_cast<const uint2*>(g_hh + (size_t)s0 * FD) + lane);
        uint2 u1 = __ldg(reinterpret_cast<const uint2*>(g_hh + (size_t)s1 * FD) + lane);
        uint2 u2 = __ldg(reinterpret_cast<const uint2*>(g_hh + (size_t)s2 * FD) + lane);
        uint2 u3 = __ldg(reinterpret_cast<const uint2*>(g_hh + (size_t)s3 * FD) + lane);
#pragma unroll
        for (int q = 0; q < 4; q++) {
            uint2 u = (q == 0) ? u0 : (q == 1) ? u1 : (q == 2) ? u2 : u3;
            float2 fa = __half22float2(*reinterpret_cast<__half2*>(&u.x));
            float2 fb = __half22float2(*reinterpret_cast<__half2*>(&u.y));
            acc.x += fa.x; acc.y += fa.y; acc.z += fb.x; acc.w += fb.y;
        }
    }
    for (; j < end; j++) {
        int s0 = __ldg(&g_esrc[j]);
        uint2 u = __ldg(reinterpret_cast<const uint2*>(g_hh + (size_t)s0 * FD) + lane);
        float2 fa = __half22float2(*reinterpret_cast<__half2*>(&u.x));
        float2 fb = __half22float2(*reinterpret_cast<__half2*>(&u.y));
        acc.x += fa.x; acc.y += fa.y; acc.z += fb.x; acc.w += fb.y;
    }

    const float nd = rsqrtf(fmaxf((float)__ldg(&g_ci[warp]), 1.f));
    const float4 bb = __ldg(reinterpret_cast<const float4*>(bvec) + lane);
    acc.x = acc.x * nd + bb.x; acc.y = acc.y * nd + bb.y;
    acc.z = acc.z * nd + bb.z; acc.w = acc.w * nd + bb.w;

    if (out) {
        reinterpret_cast<float4*>(out + (size_t)warp * FD)[lane] = acc;
    } else {
        const float ns = rsqrtf(fmaxf((float)__ldg(&g_co[warp]), 1.f));
        acc.x = fmaxf(acc.x, 0.f) * ns; acc.y = fmaxf(acc.y, 0.f) * ns;
        acc.z = fmaxf(acc.z, 0.f) * ns; acc.w = fmaxf(acc.w, 0.f) * ns;
        __half2 p0 = __floats2half2_rn(acc.x, acc.y);
        __half2 p1 = __floats2half2_rn(acc.z, acc.w);
        uint2 u;
        u.x = *reinterpret_cast<uint32_t*>(&p0);
        u.y = *reinterpret_cast<uint32_t*>(&p1);
        reinterpret_cast<uint2*>(g_aggh + (size_t)warp * FD)[lane] = u;
    }
}

// ---------------- Launch (R16 schedule, fork moved before prep_w) ------------
extern "C" void kernel_launch(void* const* d_in, const int* in_sizes, int n_in,
                              void* d_out, int out_size) {
    const float* features = (const float*)d_in[0];
    const int* src = (const int*)d_in[1];
    const int* dst = (const int*)d_in[2];
    const float* W1 = (const float*)d_in[3];
    const float* b1 = (const float*)d_in[4];
    const float* W2 = (const float*)d_in[5];
    const float* b2 = (const float*)d_in[6];
    float* out = (float*)d_out;

    const int M = in_sizes[0] / FD;   // 100000
    const int E = in_sizes[1];        // 1600000

    static cudaStream_t s2 = nullptr;
    static cudaEvent_t evF = nullptr, evD = nullptr, evB = nullptr;
    if (!s2) {
        cudaStreamCreateWithFlags(&s2, cudaStreamNonBlocking);
        cudaEventCreateWithFlags(&evF, cudaEventDisableTiming);
        cudaEventCreateWithFlags(&evD, cudaEventDisableTiming);
        cudaEventCreateWithFlags(&evB, cudaEventDisableTiming);
        cudaFuncSetAttribute(gemm_mma_kernel,
                             cudaFuncAttributeMaxDynamicSharedMemorySize, GEMM_SMEM);
    }

    const int T = 256;
    const int mb = (M + T - 1) / T;
    const int eb = (E + T - 1) / T;
    const int gemm_blocks = (M + 127) / 128;        // 782
    const int agg_blocks = (M * 32 + T - 1) / T;    // one warp per node
    const int nvec = M * 16;                         // uint4 per message array
    const int svb = (nvec + T - 1) / T;

    // Fork s2 from the capturing stream FIRST (capture-legal), before prep_w.
    zero_cnt_kernel<<<mb, T>>>(M);                   // tiny, on legacy pre-fork
    cudaEventRecord(evF, (cudaStream_t)0);
    cudaStreamWaitEvent(s2, evF, 0);

    // s2: counting/CSR chain — concurrent with prep_w + gemm1 on legacy.
    degree_kernel<<<eb, T, 0, s2>>>(src, dst, E);
    cudaEventRecord(evD, s2);                        // degrees ready
    scan1_kernel<<<NB1, SCAN_BS, 0, s2>>>(M);
    scan2_kernel<<<1, 512, 0, s2>>>(NB1);
    scan3_kernel<<<mb, T, 0, s2>>>(M, E);
    fill_kernel<<<eb, T, 0, s2>>>(src, dst, E);
    cudaEventRecord(evB, s2);                        // CSR ready

    // Legacy: prep + gemm1 (no degree dependency), then scale after degrees.
    prep_w_kernel<<<(FD * FD + T - 1) / T, T>>>(W1, W2);
    gemm_mma_kernel<<<gemm_blocks, 512, GEMM_SMEM>>>(features, 1, M);
    cudaStreamWaitEvent((cudaStream_t)0, evD, 0);
    scale_msg_kernel<<<svb, T>>>(nvec);

    // Join with CSR, then serial agg1 -> gemm2 -> agg2.
    cudaStreamWaitEvent((cudaStream_t)0, evB, 0);
    agg_kernel<<<agg_blocks, T>>>(b1, nullptr, M);
    gemm_mma_kernel<<<gemm_blocks, 512, GEMM_SMEM>>>(nullptr, 2, M);
    agg_kernel<<<agg_blocks, T>>>(b2, out, M);
}